// round 17
// baseline (speedup 1.0000x reference)
#include <cuda_runtime.h>
#include <cuda_fp16.h>
#include <cstdint>

#define J 4
#define BATCH 8192
#define TIN 10
#define TOUT 10
#define VDIM 11
#define NWARP 16
#define NTHREADS 512
#define MROWS 64
#define WGW 8
typedef unsigned long long u64;
typedef uint32_t u32;

#define FCA 232
#define WST 104
#define GSZ (104*104)
#define WWBST 232
#define WIHST 304
#define HP 104

#define OFF_WHH   0
#define OFF_WB2   64896
#define OFF_WIH   113152
#define OFF_VW    119840
#define OFF_BIH   124416
#define OFF_BHH   125632
#define OFF_BSUM  126848
#define OFF_WBB   128064
#define OFF_VB    128480
#define OFF_FCAB  128544
#define OFF_HM    158240
#define OFF_BUF1  184864
#define OFF_BUF2  198176
#define OFF_BUF3  211488
#define OFF_SC    224800
#define OFF_TOK   227360
#define OFF_T2    227616
#define SMEM_BYTES 228656

__device__ __half g_H [(size_t)J*BATCH*TIN*HP];
__device__ __half g_HA[(size_t)J*BATCH*TIN*HP];

__device__ __forceinline__ u32 smaddr(const void* p){ u32 a; asm("{.reg .u64 t; cvta.to.shared.u64 t, %1; cvt.u32.u64 %0, t;}":"=r"(a):"l"(p)); return a; }
__device__ __forceinline__ void fma2(u64 &d, u64 a, u64 b){
    asm("fma.rn.f32x2 %0, %1, %2, %0;" : "+l"(d) : "l"(a), "l"(b));
}
__device__ __forceinline__ u64 dup2(float x){ u64 r; asm("mov.b64 %0, {%1, %1};" : "=l"(r) : "f"(x)); return r; }
__device__ __forceinline__ float2 unpack2(u64 v){ float2 f; asm("mov.b64 {%0, %1}, %2;" : "=f"(f.x), "=f"(f.y) : "l"(v)); return f; }
__device__ __forceinline__ u64 h2f2(u32 h){
    float2 f=__half22float2(*(__half2*)&h);
    u64 r; asm("mov.b64 %0, {%1, %2};" : "=l"(r) : "f"(f.x), "f"(f.y)); return r;
}
__device__ __forceinline__ __half2 tanh_h2(__half2 x){
  __half2 r; asm("tanh.approx.f16x2 %0, %1;":"=r"(*(u32*)&r):"r"(*(u32*)&x)); return r;
}
__device__ __forceinline__ __half2 sigm_h2(float a, float b){
  __half2 t=tanh_h2(__floats2half2_rn(0.5f*a,0.5f*b));
  const __half2 hh=__floats2half2_rn(0.5f,0.5f);
  return __hfma2(t,hh,hh);
}
__device__ __forceinline__ __half2 tanh2f(float a, float b){
  return tanh_h2(__floats2half2_rn(a,b));
}
__device__ __forceinline__ void ldsm4(u32&a0,u32&a1,u32&a2,u32&a3,u32 ad){
  asm volatile("ldmatrix.sync.aligned.m8n8.x4.shared.b16 {%0,%1,%2,%3},[%4];":"=r"(a0),"=r"(a1),"=r"(a2),"=r"(a3):"r"(ad));
}
__device__ __forceinline__ void ldsm2(u32&b0,u32&b1,u32 ad){
  asm volatile("ldmatrix.sync.aligned.m8n8.x2.shared.b16 {%0,%1},[%2];":"=r"(b0),"=r"(b1):"r"(ad));
}
__device__ __forceinline__ void stsm4(u32 ad,u32 x0,u32 x1,u32 x2,u32 x3){
  asm volatile("stmatrix.sync.aligned.m8n8.x4.shared.b16 [%0],{%1,%2,%3,%4};"::"r"(ad),"r"(x0),"r"(x1),"r"(x2),"r"(x3):"memory");
}
__device__ __forceinline__ void stsm2(u32 ad,u32 x0,u32 x1){
  asm volatile("stmatrix.sync.aligned.m8n8.x2.shared.b16 [%0],{%1,%2};"::"r"(ad),"r"(x0),"r"(x1):"memory");
}
__device__ __forceinline__ void mma_(float d[4], const u32 a[4], u32 b0,u32 b1){
  asm("mma.sync.aligned.m16n8k16.row.col.f32.f16.f16.f32 {%0,%1,%2,%3},{%4,%5,%6,%7},{%8,%9},{%0,%1,%2,%3};"
   :"+f"(d[0]),"+f"(d[1]),"+f"(d[2]),"+f"(d[3]):"r"(a[0]),"r"(a[1]),"r"(a[2]),"r"(a[3]),"r"(b0),"r"(b1));
}
#define BARWG() asm volatile("bar.sync %0, 256;"::"r"(wg+1):"memory")

__device__ __forceinline__ void ldA7h(u32 Af[7][4], u32 fcA_sm, int row0h, int acol, int lane){
  int arow=row0h+(lane&7)+((lane&8)?8:0);
  u32 base=fcA_sm+(u32)((arow*FCA+acol+((lane&16)?8:0))*2);
  #pragma unroll
  for(int kt=0;kt<7;kt++) ldsm4(Af[kt][0],Af[kt][1],Af[kt][2],Af[kt][3],base+kt*32u);
}

// one B load serves both 16-row halves (M=32 per group)
__device__ __forceinline__ void unit_mma32(const u32 Af[2][7][4], u32 bbase, int bst,
                                           int un, float d[2][2][4], int lane){
  if(un<6){
    int row=un*16+(lane&7)+((lane&16)?8:0);
    u32 ba=bbase+(u32)((row*bst+((lane&8)?8:0))*2);
    #pragma unroll
    for(int kt=0;kt<7;kt++){
      u32 b0,b1,b2,b3; ldsm4(b0,b1,b2,b3,ba+kt*32u);
      mma_(d[0][0],Af[0][kt],b0,b1); mma_(d[0][1],Af[0][kt],b2,b3);
      mma_(d[1][0],Af[1][kt],b0,b1); mma_(d[1][1],Af[1][kt],b2,b3);
    }
  }else{
    int l16=lane&15;
    u32 ba=bbase+(u32)(((96+(l16&7))*bst+((l16&8)?8:0))*2);
    #pragma unroll
    for(int kt=0;kt<7;kt++){
      u32 b0,b1; ldsm2(b0,b1,ba+kt*32u);
      mma_(d[0][0],Af[0][kt],b0,b1);
      mma_(d[1][0],Af[1][kt],b0,b1);
    }
  }
}

__device__ __forceinline__ u32 stsm_addr(u32 base_sm,int row0,int stride,int c0,int lane){
  int row=row0+(lane&15), col=c0+((lane>>4)<<3);
  return base_sm + (u32)((row*stride+col)*2);
}

// encoder (f32) rz epilogue, both halves
__device__ __forceinline__ void rz_epi32(int gate,int un,float d[2][2][4],
    const __half* wih,const float* bsum,const int* toks,
    u32 buf2_sm,u32 buf3_sm,int row0,int g,int tig,int lane){
  int ns=(un<6)?2:1;
  #pragma unroll
  for(int rh=0;rh<2;rh++){
    u32 x[4]={0,0,0,0};
    #pragma unroll
    for(int s=0;s<2;s++){
      if(s<ns){
        int c=un*16+8*s+2*tig, gc=gate*100+c;
        float2 bs=*(const float2*)&bsum[gc];
        #pragma unroll
        for(int h2=0;h2<2;h2++){
          int r=row0+16*rh+g+8*h2;
          float2 w=__half22float2(*(const __half2*)&wih[toks[r]*WIHST+gc]);
          __half2 v=sigm_h2(d[rh][s][2*h2]+w.x+bs.x, d[rh][s][2*h2+1]+w.y+bs.y);
          x[2*s+h2]=*(u32*)&v;
        }
      }
    }
    u32 ad=stsm_addr(gate?buf3_sm:buf2_sm,row0+16*rh,104,un*16,lane);
    if(ns==2) stsm4(ad,x[0],x[1],x[2],x[3]); else stsm2(ad,x[0],x[1]);
  }
}

// decoder (half2) rz epilogue, both halves
__device__ __forceinline__ void rz_epi32_h2(int gate,int un,float d[2][2][4],
    const __half* wih,const __half2* bsum2,const int* toks,
    u32 buf2_sm,u32 buf3_sm,int row0,int g,int tig,int lane){
  const __half2 hh5=__floats2half2_rn(0.5f,0.5f);
  int ns=(un<6)?2:1;
  #pragma unroll
  for(int rh=0;rh<2;rh++){
    u32 x[4]={0,0,0,0};
    #pragma unroll
    for(int s=0;s<2;s++){
      if(s<ns){
        int c=un*16+8*s+2*tig, gc=gate*100+c;
        __half2 bs=bsum2[gate*52+(c>>1)];
        #pragma unroll
        for(int h2=0;h2<2;h2++){
          int r=row0+16*rh+g+8*h2;
          __half2 w=*(const __half2*)&wih[toks[r]*WIHST+gc];
          __half2 dd=__floats2half2_rn(d[rh][s][2*h2],d[rh][s][2*h2+1]);
          __half2 t=tanh_h2(__hmul2(__hadd2(__hadd2(dd,w),bs),hh5));
          __half2 v=__hfma2(t,hh5,hh5);
          x[2*s+h2]=*(u32*)&v;
        }
      }
    }
    u32 ad=stsm_addr(gate?buf3_sm:buf2_sm,row0+16*rh,104,un*16,lane);
    if(ns==2) stsm4(ad,x[0],x[1],x[2],x[3]); else stsm2(ad,x[0],x[1]);
  }
}

__device__ __forceinline__ int n_unit_of(int wl){
  return (wl<5)? ((wl==4)?6:wl+2) : (wl>=6? wl-6 : -1);
}

// encoder pass A (M=32): rz + n(nacc) in combined loop; ha separate (same Af)
__device__ __forceinline__ void enc_passA32(u32 fcA_sm,int row0,int acol,u32 whh_sm,u32 aw_sm,
    const __half* wih,const float* bsum,const int* toks,
    u32 buf2_sm,u32 buf3_sm,int tprev,int blk0,int wl,int lane,bool do_ha,bool t0,
    float nacc[2][2][4]){
  int g=lane>>2,tig=lane&3;
  if(t0){
    for(int u=wl;u<14;u+=WGW){
      int gate=u/7, un=u-7*gate;
      float dz[2][2][4]={{{0,0,0,0},{0,0,0,0}},{{0,0,0,0},{0,0,0,0}}};
      rz_epi32(gate,un,dz,wih,bsum,toks,buf2_sm,buf3_sm,row0,g,tig,lane);
    }
    return;
  }
  u32 Af[2][7][4];
  ldA7h(Af[0],fcA_sm,row0,acol,lane);
  ldA7h(Af[1],fcA_sm,row0+16,acol,lane);
  for(int u=wl;u<21;u+=WGW){
    if(u<14){
      int gate=u/7, un=u-7*gate;
      float d[2][2][4]={{{0,0,0,0},{0,0,0,0}},{{0,0,0,0},{0,0,0,0}}};
      unit_mma32(Af,whh_sm+(u32)(gate*GSZ*2),WST,un,d,lane);
      rz_epi32(gate,un,d,wih,bsum,toks,buf2_sm,buf3_sm,row0,g,tig,lane);
    }else{
      unit_mma32(Af,whh_sm+(u32)(2*GSZ*2),WST,u-14,nacc,lane);
    }
  }
  if(do_ha && wl<7){
    int un=wl;
    float d[2][2][4]={{{0,0,0,0},{0,0,0,0}},{{0,0,0,0},{0,0,0,0}}};
    unit_mma32(Af,aw_sm,WST,un,d,lane);
    int ns=(un<6)?2:1;
    #pragma unroll
    for(int rh=0;rh<2;rh++){
      #pragma unroll
      for(int s=0;s<2;s++){
        if(s<ns){
          int c=un*16+8*s+2*tig;
          #pragma unroll
          for(int h2=0;h2<2;h2++){
            int r=row0+16*rh+g+8*h2;
            int bb=blk0+(r>>2);
            *(__half2*)&g_HA[((size_t)(bb*J+(r&3))*TIN+tprev)*HP+c]=__floats2half2_rn(d[rh][s][2*h2],d[rh][s][2*h2+1]);
          }
        }
      }
    }
  }
}

// encoder n epilogue (one unit per warp)
__device__ __forceinline__ void gru_n_epi_enc32(float nacc[2][2][4],int un,int row0,
    const __half* wih,const float* bih,const float* bhh,const int* toks,
    const __half* buf2,const __half* buf3,float* hm,u32 fcA_sm,int wcol,
    int t,int blk0,int lane){
  if(un<0) return;
  int g=lane>>2,tig=lane&3, ns=(un<6)?2:1;
  #pragma unroll
  for(int rh=0;rh<2;rh++){
    u32 x[4]={0,0,0,0};
    #pragma unroll
    for(int s=0;s<2;s++){
      if(s<ns){
        int c=un*16+8*s+2*tig, gc=200+c;
        float2 bi=*(const float2*)&bih[gc], bh=*(const float2*)&bhh[gc];
        #pragma unroll
        for(int h2=0;h2<2;h2++){
          int r=row0+16*rh+g+8*h2;
          float2 w=__half22float2(*(const __half2*)&wih[toks[r]*WIHST+gc]);
          float2 rr=__half22float2(*(const __half2*)&buf2[r*104+c]);
          float2 zz=__half22float2(*(const __half2*)&buf3[r*104+c]);
          __half2 nh=tanh2f(w.x+bi.x+rr.x*(nacc[rh][s][2*h2]+bh.x),
                            w.y+bi.y+rr.y*(nacc[rh][s][2*h2+1]+bh.y));
          float2 nn=__half22float2(nh);
          float2 ho=*(const float2*)&hm[r*104+c];
          float2 hn; hn.x=(1.f-zz.x)*nn.x+zz.x*ho.x; hn.y=(1.f-zz.y)*nn.y+zz.y*ho.y;
          *(float2*)&hm[r*104+c]=hn;
          __half2 hh=__floats2half2_rn(hn.x,hn.y);
          x[2*s+h2]=*(u32*)&hh;
          int bb=blk0+(r>>2);
          *(__half2*)&g_H[((size_t)(bb*J+(r&3))*TIN+t)*HP+c]=hh;
        }
      }
    }
    u32 ad=stsm_addr(fcA_sm,row0+16*rh,FCA,wcol+un*16,lane);
    if(ns==2) stsm4(ad,x[0],x[1],x[2],x[3]); else stsm2(ad,x[0],x[1]);
  }
}

// decoder n epilogue (half2), one unit per warp
__device__ __forceinline__ void gru_n_epi_dec32(float nacc[2][2][4],int un,int row0,
    const __half* wih,const __half2* bin2,const __half2* bhn2,const int* toks,
    const __half* buf2,const __half* buf3,const __half* fcA,u32 fcA_sm,int lane){
  if(un<0) return;
  int g=lane>>2,tig=lane&3, ns=(un<6)?2:1;
  #pragma unroll
  for(int rh=0;rh<2;rh++){
    u32 x[4]={0,0,0,0};
    #pragma unroll
    for(int s=0;s<2;s++){
      if(s<ns){
        int c=un*16+8*s+2*tig, gc=200+c;
        __half2 bi=bin2[c>>1], bh=bhn2[c>>1];
        #pragma unroll
        for(int h2=0;h2<2;h2++){
          int r=row0+16*rh+g+8*h2;
          __half2 w=*(const __half2*)&wih[toks[r]*WIHST+gc];
          __half2 rr=*(const __half2*)&buf2[r*104+c];
          __half2 zz=*(const __half2*)&buf3[r*104+c];
          __half2 dd=__floats2half2_rn(nacc[rh][s][2*h2],nacc[rh][s][2*h2+1]);
          __half2 nh=tanh_h2(__hfma2(rr,__hadd2(dd,bh),__hadd2(w,bi)));
          __half2 ho=*(const __half2*)&fcA[r*FCA+112+c];
          __half2 hh=__hfma2(zz,__hsub2(ho,nh),nh);
          x[2*s+h2]=*(u32*)&hh;
        }
      }
    }
    u32 ad=stsm_addr(fcA_sm,row0+16*rh,FCA,un*16,lane);
    if(ns==2) stsm4(ad,x[0],x[1],x[2],x[3]); else stsm2(ad,x[0],x[1]);
  }
}

// decoder pass A (M=32): rz+n combined; fc last (Af0 loaded after Af1 dies)
__device__ __forceinline__ void dec_passA32(u32 fcA_sm,int row0,u32 whh_sm,u32 wb2_sm,
    const __half* wih,const __half2* bsum2,const __half2* wbb2,const int* toks,
    u32 buf1_sm,u32 buf2_sm,u32 buf3_sm,int wl,int lane,float nacc[2][2][4]){
  int g=lane>>2,tig=lane&3;
  float dfc[2][2][4]={{{0,0,0,0},{0,0,0,0}},{{0,0,0,0},{0,0,0,0}}};
  {
    u32 Af1[2][7][4];
    ldA7h(Af1[0],fcA_sm,row0,112,lane);
    ldA7h(Af1[1],fcA_sm,row0+16,112,lane);
    for(int u=wl;u<21;u+=WGW){
      if(u<14){
        int gate=u/7, un=u-7*gate;
        float d[2][2][4]={{{0,0,0,0},{0,0,0,0}},{{0,0,0,0},{0,0,0,0}}};
        unit_mma32(Af1,whh_sm+(u32)(gate*GSZ*2),WST,un,d,lane);
        rz_epi32_h2(gate,un,d,wih,bsum2,toks,buf2_sm,buf3_sm,row0,g,tig,lane);
      }else{
        unit_mma32(Af1,whh_sm+(u32)(2*GSZ*2),WST,u-14,nacc,lane);
      }
    }
    if(wl<7) unit_mma32(Af1,wb2_sm+(u32)(112*2),WWBST,wl,dfc,lane);
  }
  if(wl<7){
    int un=wl;
    u32 Af0[2][7][4];
    ldA7h(Af0[0],fcA_sm,row0,0,lane);
    ldA7h(Af0[1],fcA_sm,row0+16,0,lane);
    unit_mma32(Af0,wb2_sm,WWBST,un,dfc,lane);
    int ns=(un<6)?2:1;
    #pragma unroll
    for(int rh=0;rh<2;rh++){
      u32 x[4]={0,0,0,0};
      #pragma unroll
      for(int s=0;s<2;s++){
        if(s<ns){
          int c=un*16+8*s+2*tig;
          __half2 wb=wbb2[c>>1];
          #pragma unroll
          for(int h2=0;h2<2;h2++){
            __half2 dd=__floats2half2_rn(dfc[rh][s][2*h2],dfc[rh][s][2*h2+1]);
            __half2 v=tanh_h2(__hadd2(dd,wb));
            x[2*s+h2]=*(u32*)&v;
          }
        }
      }
      u32 ad=stsm_addr(buf1_sm,row0+16*rh,104,un*16,lane);
      if(ns==2) stsm4(ad,x[0],x[1],x[2],x[3]); else stsm2(ad,x[0],x[1]);
    }
  }
}

__global__ void __launch_bounds__(NTHREADS,1)
fused_kernel(const int* __restrict__ inputs, const int* __restrict__ target,
             const float* __restrict__ eWih, const float* __restrict__ eWhh,
             const float* __restrict__ ebih, const float* __restrict__ ebhh,
             const float* __restrict__ dWih, const float* __restrict__ dWhh,
             const float* __restrict__ dbih, const float* __restrict__ dbhh,
             const float* __restrict__ Ww,  const float* __restrict__ Wb,
             const float* __restrict__ Vw,  const float* __restrict__ Vb,
             const float* __restrict__ Aw,  float* __restrict__ out)
{
    extern __shared__ char smx[];
    __half* whh =(__half*)(smx+OFF_WHH);
    __half* wb2 =(__half*)(smx+OFF_WB2);
    __half* wih =(__half*)(smx+OFF_WIH);
    float*  vwf =(float*)(smx+OFF_VW);
    float*  bih =(float*)(smx+OFF_BIH);
    float*  bhh =(float*)(smx+OFF_BHH);
    float*  bsum=(float*)(smx+OFF_BSUM);
    float*  wbb =(float*)(smx+OFF_WBB);
    float*  vbb =(float*)(smx+OFF_VB);
    __half* fcA =(__half*)(smx+OFF_FCAB);
    float*  hm  =(float*)(smx+OFF_HM);
    __half* buf1=(__half*)(smx+OFF_BUF1);
    __half* buf2=(__half*)(smx+OFF_BUF2);
    __half* buf3=(__half*)(smx+OFF_BUF3);
    float*  scb =(float*)(smx+OFF_SC);
    int*    toks=(int*)(smx+OFF_TOK);
    __half2* bsum2=(__half2*)(smx+OFF_T2);
    __half2* bin2 = bsum2+104;
    __half2* bhn2 = bin2+52;
    __half2* wbb2 = bhn2+52;

    const u32 fcA_sm=smaddr(fcA), whh_sm=smaddr(whh), wb2_sm=smaddr(wb2);
    const u32 buf1_sm=smaddr(buf1), buf2_sm=smaddr(buf2), buf3_sm=smaddr(buf3);
    const int tid=threadIdx.x, warp=tid>>5, lane=tid&31;
    const int wg=warp>>3, wl=warp&7, row0=wg*32;
    const int un_n = n_unit_of(wl);
    const int blk0=blockIdx.x*NWARP;
    const int b=blk0+warp;
    const int e0=2*lane, e1=64+2*lane;
    const bool m1=(lane<18);

    for(int i=tid;i<3*GSZ;i+=NTHREADS){
        int gate=i/GSZ, rem=i-gate*GSZ, n=rem/WST, k=rem-n*WST;
        whh[i]=(n<100&&k<100)?__float2half(eWhh[(gate*100+n)*100+k]):__half(0.f);
    }
    for(int i=tid;i<104*WST;i+=NTHREADS){
        int f=i/WST,e=i-f*WST;
        wb2[i]=(f<100&&e<100)?__float2half(Aw[e*100+f]):__half(0.f);
    }
    for(int i=tid;i<11*WIHST;i+=NTHREADS){
        int v=i/WIHST,gg=i-v*WIHST;
        wih[i]=(gg<300)?__float2half(eWih[gg*11+v]):__half(0.f);
    }
    for(int i=tid;i<304;i+=NTHREADS){
        float a=(i<300)?ebih[i]:0.f, c=(i<300)?ebhh[i]:0.f;
        bih[i]=a; bhh[i]=c; bsum[i]=a+c;
    }
    for(int i=tid;i<MROWS*FCA/2;i+=NTHREADS) ((u32*)fcA)[i]=0u;
    for(int i=tid;i<MROWS*104;i+=NTHREADS) hm[i]=0.f;
    int* toks2=(int*)scb;
    for(int i=tid;i<TIN*MROWS;i+=NTHREADS){
        int t=i/MROWS, r=i-t*MROWS;
        int bb=blk0+(r>>2);
        toks2[i]=inputs[((r&3)*TIN+t)*BATCH+bb];
    }
    __syncthreads();

    for(int t=0;t<TIN;t++){
        int rcol=(t&1)?112:0, wcol=112-rcol;
        float nacc[2][2][4]={{{0,0,0,0},{0,0,0,0}},{{0,0,0,0},{0,0,0,0}}};
        enc_passA32(fcA_sm,row0,rcol,whh_sm,wb2_sm,wih,bsum,&toks2[t*MROWS],
                    buf2_sm,buf3_sm,t-1,blk0,wl,lane,t>0,t==0,nacc);
        BARWG();
        gru_n_epi_enc32(nacc,un_n,row0,wih,bih,bhh,&toks2[t*MROWS],buf2,buf3,hm,fcA_sm,wcol,t,blk0,lane);
        BARWG();
    }
    if(wl<7){   // final HA(9): h(9) mirror at col 0
        int g=lane>>2,tig=lane&3;
        u32 Af[2][7][4];
        ldA7h(Af[0],fcA_sm,row0,0,lane);
        ldA7h(Af[1],fcA_sm,row0+16,0,lane);
        int un=wl;
        float d[2][2][4]={{{0,0,0,0},{0,0,0,0}},{{0,0,0,0},{0,0,0,0}}};
        unit_mma32(Af,wb2_sm,WST,un,d,lane);
        int ns=(un<6)?2:1;
        #pragma unroll
        for(int rh=0;rh<2;rh++){
            #pragma unroll
            for(int s=0;s<2;s++){
                if(s<ns){
                    int c=un*16+8*s+2*tig;
                    #pragma unroll
                    for(int h2=0;h2<2;h2++){
                        int r=row0+16*rh+g+8*h2;
                        int bb=blk0+(r>>2);
                        *(__half2*)&g_HA[((size_t)(bb*J+(r&3))*TIN+(TIN-1))*HP+c]=__floats2half2_rn(d[rh][s][2*h2],d[rh][s][2*h2+1]);
                    }
                }
            }
        }
    }
    __syncthreads();

    for(int i=tid;i<3*GSZ;i+=NTHREADS){
        int gate=i/GSZ, rem=i-gate*GSZ, n=rem/WST, k=rem-n*WST;
        whh[i]=(n<100&&k<100)?__float2half(dWhh[(gate*100+n)*100+k]):__half(0.f);
    }
    for(int i=tid;i<104*WWBST;i+=NTHREADS){
        int e=i/WWBST, kk=i-e*WWBST;
        float v=0.f;
        if(e<100){ if(kk<100) v=Ww[e*200+kk]; else if(kk>=112&&kk<212) v=Ww[e*200+kk-12]; }
        wb2[i]=__float2half(v);
    }
    for(int i=tid;i<11*WIHST;i+=NTHREADS){
        int v=i/WIHST,gg=i-v*WIHST;
        wih[i]=(gg<300)?__float2half(dWih[gg*11+v]):__half(0.f);
    }
    for(int i=tid;i<304;i+=NTHREADS){
        float a=(i<300)?dbih[i]:0.f, c=(i<300)?dbhh[i]:0.f;
        bih[i]=a; bhh[i]=c; bsum[i]=a+c;
    }
    for(int i=tid;i<11*104;i+=NTHREADS){int v=i/104,e=i-v*104; vwf[i]=(e<100)?Vw[v*100+e]:0.f;}
    for(int i=tid;i<104;i+=NTHREADS) wbb[i]=(i<100)?Wb[i]:0.f;
    for(int i=tid;i<16;i+=NTHREADS) vbb[i]=(i<VDIM)?Vb[i]:0.f;
    for(int i=tid;i<MROWS*112;i+=NTHREADS){int r=i/112,c=i-r*112; fcA[r*FCA+112+c]=fcA[r*FCA+c];}
    if(tid<MROWS) toks[tid]=VDIM-1;
    __syncthreads();
    for(int i=tid;i<52;i+=NTHREADS){
        int c=2*i;
        bsum2[i]   =__floats2half2_rn(bsum[c],bsum[c+1]);
        bsum2[52+i]=__floats2half2_rn(bsum[100+c],bsum[100+c+1]);
        bin2[i]=__floats2half2_rn(bih[200+c],bih[200+c+1]);
        bhn2[i]=__floats2half2_rn(bhh[200+c],bhh[200+c+1]);
        wbb2[i]=__floats2half2_rn(wbb[c],wbb[c+1]);
    }
    __syncthreads();

    {   // init P0: rz+n on c-mirror (region1), epilogue writes P-mirror
        float nacc[2][2][4]={{{0,0,0,0},{0,0,0,0}},{{0,0,0,0},{0,0,0,0}}};
        u32 Af1[2][7][4];
        ldA7h(Af1[0],fcA_sm,row0,112,lane);
        ldA7h(Af1[1],fcA_sm,row0+16,112,lane);
        int g=lane>>2,tig=lane&3;
        for(int u=wl;u<21;u+=WGW){
          if(u<14){
            int gate=u/7, un=u-7*gate;
            float d[2][2][4]={{{0,0,0,0},{0,0,0,0}},{{0,0,0,0},{0,0,0,0}}};
            unit_mma32(Af1,whh_sm+(u32)(gate*GSZ*2),WST,un,d,lane);
            rz_epi32_h2(gate,un,d,wih,bsum2,toks,buf2_sm,buf3_sm,row0,g,tig,lane);
          }else{
            unit_mma32(Af1,whh_sm+(u32)(2*GSZ*2),WST,u-14,nacc,lane);
          }
        }
        BARWG();
        gru_n_epi_dec32(nacc,un_n,row0,wih,bin2,bhn2,toks,buf2,buf3,fcA,fcA_sm,lane);
        BARWG();
    }

    float score=0.f;
    float* sc=&scb[warp*40];
    for(int t=0;t<TOUT;t++){
        {   // scores = HA . P  (packed f32x2)
            int j=lane/10, tt=lane-10*j;
            const uint4* hap=(const uint4*)&g_HA[((size_t)(b*J+j)*TIN+tt)*HP];
            const uint4* pj =(const uint4*)&fcA[(warp*J+j)*FCA];
            u64 acc=0ull;
            #pragma unroll 13
            for(int q=0;q<13;q++){
                uint4 hv=hap[q], pv4=pj[q];
                fma2(acc,h2f2(hv.x),h2f2(pv4.x));
                fma2(acc,h2f2(hv.y),h2f2(pv4.y));
                fma2(acc,h2f2(hv.z),h2f2(pv4.z));
                fma2(acc,h2f2(hv.w),h2f2(pv4.w));
            }
            float2 fz=unpack2(acc); sc[lane]=fz.x+fz.y;
            if(lane<8){
                int t2=32+lane, j2=t2/10, tt2=t2-10*j2;
                const uint4* hap2=(const uint4*)&g_HA[((size_t)(b*J+j2)*TIN+tt2)*HP];
                const uint4* pj2 =(const uint4*)&fcA[(warp*J+j2)*FCA];
                u64 a2=0ull;
                #pragma unroll 13
                for(int q=0;q<13;q++){
                    uint4 hv=hap2[q], pv4=pj2[q];
                    fma2(a2,h2f2(hv.x),h2f2(pv4.x));
                    fma2(a2,h2f2(hv.y),h2f2(pv4.y));
                    fma2(a2,h2f2(hv.z),h2f2(pv4.z));
                    fma2(a2,h2f2(hv.w),h2f2(pv4.w));
                }
                float2 f2z=unpack2(a2); sc[t2]=f2z.x+f2z.y;
            }
        }
        __syncwarp();
        if(lane<J){
            float mx=-1e30f;
            #pragma unroll
            for(int tt=0;tt<TIN;tt++) mx=fmaxf(mx,sc[lane*10+tt]);
            float s=0.f;
            #pragma unroll
            for(int tt=0;tt<TIN;tt++) s+=__expf(sc[lane*10+tt]-mx);
            float lg=__logf(s)+mx;
            #pragma unroll
            for(int tt=0;tt<TIN;tt++) sc[lane*10+tt]-=lg;
        }
        __syncwarp();
        {   // c = logs . H  (packed f32x2; 52 tasks)
            #pragma unroll
            for(int pass=0;pass<2;pass++){
                int task = pass? 32+lane : lane;
                if(pass && lane>=20) break;
                int j=task/13, q=task-13*j;
                const uint4* hb=(const uint4*)&g_H[((size_t)(b*J+j)*TIN)*HP];
                u64 A0=0ull,A1=0ull,A2=0ull,A3=0ull;
                #pragma unroll
                for(int tt=0;tt<TIN;tt++){
                    u64 lg2=dup2(sc[j*10+tt]);
                    uint4 hv=hb[tt*13+q];
                    fma2(A0,h2f2(hv.x),lg2);
                    fma2(A1,h2f2(hv.y),lg2);
                    fma2(A2,h2f2(hv.z),lg2);
                    fma2(A3,h2f2(hv.w),lg2);
                }
                int r=warp*J+j;
                float2 f0=unpack2(A0),f1=unpack2(A1),f2=unpack2(A2),f3=unpack2(A3);
                __half2 p0=__floats2half2_rn(f0.x,f0.y), p1=__floats2half2_rn(f1.x,f1.y);
                __half2 p2=__floats2half2_rn(f2.x,f2.y), p3=__floats2half2_rn(f3.x,f3.y);
                uint4 pk; pk.x=*(u32*)&p0; pk.y=*(u32*)&p1; pk.z=*(u32*)&p2; pk.w=*(u32*)&p3;
                *(uint4*)&fcA[r*FCA+112+8*q]=pk;
            }
        }
        if(lane<J) toks[warp*J+lane]=target[t*BATCH+b];
        BARWG();
        float nacc[2][2][4]={{{0,0,0,0},{0,0,0,0}},{{0,0,0,0},{0,0,0,0}}};
        dec_passA32(fcA_sm,row0,whh_sm,wb2_sm,wih,bsum2,wbb2,toks,buf1_sm,buf2_sm,buf3_sm,wl,lane,nacc);
        BARWG();
        {   // logits
            __half2 mA2=__floats2half2_rn(-60000.f,-60000.f), mB2=mA2;
            #pragma unroll
            for(int j=0;j<J;j++){
                int r=warp*J+j;
                mA2=__hmax2(mA2,*(const __half2*)&buf1[r*104+e0]);
                if(m1) mB2=__hmax2(mB2,*(const __half2*)&buf1[r*104+e1]);
            }
            float2 mA=__half22float2(mA2);
            float2 mB=m1?__half22float2(mB2):make_float2(0.f,0.f);
            float pv[VDIM];
            #pragma unroll
            for(int v=0;v<VDIM;v++){
                const float* vr=&vwf[v*104];
                float p=vr[e0]*mA.x+vr[e0+1]*mA.y;
                if(m1){p=fmaf(vr[e1],mB.x,p); p=fmaf(vr[e1+1],mB.y,p);}
                pv[v]=p;
            }
            #pragma unroll
            for(int off=16;off>=1;off>>=1){
                #pragma unroll
                for(int v=0;v<VDIM;v++) pv[v]+=__shfl_xor_sync(0xffffffffu,pv[v],off);
            }
            int tok=target[t*BATCH+b];
            float mx=-1e30f;
            #pragma unroll
            for(int v=0;v<VDIM;v++){pv[v]+=vbb[v]; mx=fmaxf(mx,pv[v]);}
            float ss=0.f;
            #pragma unroll
            for(int v=0;v<VDIM;v++) ss+=__expf(pv[v]-mx);
            score+=pv[tok]-mx-__logf(ss);
        }
        gru_n_epi_dec32(nacc,un_n,row0,wih,bin2,bhn2,toks,buf2,buf3,fcA,fcA_sm,lane);
        BARWG();
    }
    if(lane==0) out[b]=score;
}

extern "C" void kernel_launch(void* const* d_in, const int* in_sizes, int n_in,
                              void* d_out, int out_size)
{
    cudaFuncSetAttribute(fused_kernel, cudaFuncAttributeMaxDynamicSharedMemorySize, SMEM_BYTES);
    int grid=(BATCH+NWARP-1)/NWARP;
    fused_kernel<<<grid, NTHREADS, SMEM_BYTES>>>(
        (const int*)d_in[0], (const int*)d_in[1],
        (const float*)d_in[2], (const float*)d_in[3], (const float*)d_in[4], (const float*)d_in[5],
        (const float*)d_in[6], (const float*)d_in[7], (const float*)d_in[8], (const float*)d_in[9],
        (const float*)d_in[10], (const float*)d_in[11], (const float*)d_in[12], (const float*)d_in[13],
        (const float*)d_in[14], (float*)d_out);
}